// round 3
// baseline (speedup 1.0000x reference)
#include <cuda_runtime.h>
#include <cuda_bf16.h>
#include <cstdint>

// Problem constants (fixed by the dataset)
#define NNODES 100000
#define FIN    500
#define H1     128
#define H2     64
#define NC     10

// ---------------- scratch (device globals; no allocs allowed) ----------------
__device__ __align__(16) float g_dis [NNODES];       // deg -> rsqrt(deg)
__device__ __align__(16) float g_hs1 [NNODES * H1];  // dis[i] * (x@W1)[i]
__device__ __align__(16) float g_acc1[NNODES * H1];  // scatter accum -> layer1 out h
__device__ __align__(16) float g_hs2 [NNODES * H2];  // dis[i] * (h@W2)[i]
__device__ __align__(16) float g_acc2[NNODES * H2];  // scatter accum (layer2)
__device__ int g_is64;                               // edge_index underlying dtype flag

// ---------------- probe: detect int64 vs int32 edge_index layout -------------
// If the buffer is little-endian int64 with values < 2^31, every odd 32-bit
// word of the first 1024 entries is zero. For int32 data those words are
// random node indices (P[all 1024 == 0] ~ 0).
__global__ void k_probe(const unsigned* __restrict__ w) {
    __shared__ unsigned red[256];
    unsigned o = 0;
    for (int i = threadIdx.x; i < 1024; i += 256) o |= w[2 * i + 1];
    red[threadIdx.x] = o;
    __syncthreads();
    for (int s = 128; s; s >>= 1) {
        if (threadIdx.x < s) red[threadIdx.x] |= red[threadIdx.x + s];
        __syncthreads();
    }
    if (threadIdx.x == 0) g_is64 = (red[0] == 0u) ? 1 : 0;
}

__device__ __forceinline__ int eidx(const void* __restrict__ ei, long pos) {
    if (g_is64) return (int)((const long long*)ei)[pos];
    return ((const int*)ei)[pos];
}

// ---------------- init: deg=1 (self loop), zero accumulators ----------------
__global__ void k_init() {
    int i = blockIdx.x * blockDim.x + threadIdx.x;
    int stride = gridDim.x * blockDim.x;
    for (int j = i; j < NNODES; j += stride) g_dis[j] = 1.0f;
    float4 z = make_float4(0.f, 0.f, 0.f, 0.f);
    const int n1 = NNODES * H1 / 4;
    for (int j = i; j < n1; j += stride) reinterpret_cast<float4*>(g_acc1)[j] = z;
    const int n2 = NNODES * H2 / 4;
    for (int j = i; j < n2; j += stride) reinterpret_cast<float4*>(g_acc2)[j] = z;
}

// ---------------- degree: atomicAdd 1 per edge into g_dis -------------------
__global__ void k_degree(const void* __restrict__ ei, int E) {
    int i = blockIdx.x * blockDim.x + threadIdx.x;
    if (i < E) {
        int d = eidx(ei, (long)E + i);   // dst = second row
        atomicAdd(&g_dis[d], 1.0f);
    }
}

__global__ void k_rsqrt() {
    int i = blockIdx.x * blockDim.x + threadIdx.x;
    if (i < NNODES) g_dis[i] = rsqrtf(g_dis[i]);
}

// ---------------- GEMM with per-row scale epilogue ---------------------------
// Cout[row, col] = g_dis[row] * sum_k A[row,k] * B[k,col]
// BN == Ncols (single column-block). Classic SMEM-tiled SGEMM.
template <int BM, int BN, int BK, int TM, int TN>
__global__ __launch_bounds__(256) void k_gemm_scale(
    const float* __restrict__ A, const float* __restrict__ B,
    float* __restrict__ Cout, int M, int K, int Ncols)
{
    __shared__ float As[BK][BM];
    __shared__ float Bs[BK][BN];
    constexpr int NT = (BM / TM) * (BN / TN);   // 256
    const int tid = threadIdx.x;
    const int tx = tid % (BN / TN);
    const int ty = tid / (BN / TN);
    const int rowBase = blockIdx.x * BM;

    float acc[TM][TN];
    #pragma unroll
    for (int m = 0; m < TM; m++)
        #pragma unroll
        for (int n = 0; n < TN; n++) acc[m][n] = 0.f;

    for (int k0 = 0; k0 < K; k0 += BK) {
        // load A tile (BM x BK), stored transposed As[kk][row]
        #pragma unroll
        for (int i = tid * 4; i < BM * BK; i += NT * 4) {
            int r = i / BK, kk = i % BK;
            int grow = rowBase + r;
            float4 v = make_float4(0.f, 0.f, 0.f, 0.f);
            if (grow < M) {
                if (k0 + kk + 3 < K) {
                    v = *reinterpret_cast<const float4*>(A + (long)grow * K + k0 + kk);
                } else {
                    float t[4];
                    #pragma unroll
                    for (int j = 0; j < 4; j++) {
                        int kg = k0 + kk + j;
                        t[j] = (kg < K) ? A[(long)grow * K + kg] : 0.f;
                    }
                    v = make_float4(t[0], t[1], t[2], t[3]);
                }
            }
            As[kk + 0][r] = v.x; As[kk + 1][r] = v.y;
            As[kk + 2][r] = v.z; As[kk + 3][r] = v.w;
        }
        // load B tile (BK x BN)
        #pragma unroll
        for (int i = tid * 4; i < BK * BN; i += NT * 4) {
            int kk = i / BN, c = i % BN;
            int gk = k0 + kk;
            float4 v = make_float4(0.f, 0.f, 0.f, 0.f);
            if (gk < K) v = *reinterpret_cast<const float4*>(B + (long)gk * Ncols + c);
            *reinterpret_cast<float4*>(&Bs[kk][c]) = v;
        }
        __syncthreads();

        #pragma unroll
        for (int kk = 0; kk < BK; kk++) {
            float a[TM], b[TN];
            #pragma unroll
            for (int m = 0; m < TM; m++) a[m] = As[kk][ty * TM + m];
            #pragma unroll
            for (int n = 0; n < TN; n++) b[n] = Bs[kk][tx * TN + n];
            #pragma unroll
            for (int m = 0; m < TM; m++)
                #pragma unroll
                for (int n = 0; n < TN; n++) acc[m][n] = fmaf(a[m], b[n], acc[m][n]);
        }
        __syncthreads();
    }

    // epilogue: scale by g_dis[row]
    #pragma unroll
    for (int m = 0; m < TM; m++) {
        int grow = rowBase + ty * TM + m;
        if (grow >= M) continue;
        float s = g_dis[grow];
        #pragma unroll
        for (int n = 0; n < TN; n += 4) {
            float4 v;
            v.x = acc[m][n + 0] * s; v.y = acc[m][n + 1] * s;
            v.z = acc[m][n + 2] * s; v.w = acc[m][n + 3] * s;
            *reinterpret_cast<float4*>(Cout + (long)grow * Ncols + tx * TN + n) = v;
        }
    }
}

// ---------------- scatter: acc[dst] += hs[src], float4 vector RED -----------
// Fq = features/4. One thread per (edge, float4-group); consecutive threads
// cover one edge's row -> coalesced gather (L2-resident), one v4 reduction.
__global__ void k_scatter(const void* __restrict__ ei,
                          const float* __restrict__ hs, float* __restrict__ acc,
                          int E, int Fq)
{
    long idx = (long)blockIdx.x * blockDim.x + threadIdx.x;
    long total = (long)E * Fq;
    if (idx >= total) return;
    int e = (int)(idx / Fq);
    int q = (int)(idx - (long)e * Fq);
    int s = eidx(ei, e);
    int d = eidx(ei, (long)E + e);
    float4 v = reinterpret_cast<const float4*>(hs)[(long)s * Fq + q];
    float* p = acc + ((long)d * Fq + q) * 4;
    asm volatile("red.global.add.v4.f32 [%0], {%1, %2, %3, %4};"
                 :: "l"(p), "f"(v.x), "f"(v.y), "f"(v.z), "f"(v.w)
                 : "memory");
}

// ---------------- layer finish: h = relu(dis*(acc+hs)+b), in-place in acc ---
__global__ void k_finish1(const float* __restrict__ b1) {
    int idx = blockIdx.x * blockDim.x + threadIdx.x;   // over N*H1/4
    const int total = NNODES * H1 / 4;
    if (idx >= total) return;
    const int fq = H1 / 4;
    int node = idx / fq;
    int q = idx - node * fq;
    float s = g_dis[node];
    float4 a = reinterpret_cast<const float4*>(g_acc1)[idx];
    float4 h = reinterpret_cast<const float4*>(g_hs1)[idx];
    float4 bb = reinterpret_cast<const float4*>(b1)[q];
    float4 r;
    r.x = fmaxf(s * (a.x + h.x) + bb.x, 0.f);
    r.y = fmaxf(s * (a.y + h.y) + bb.y, 0.f);
    r.z = fmaxf(s * (a.z + h.z) + bb.z, 0.f);
    r.w = fmaxf(s * (a.w + h.w) + bb.w, 0.f);
    reinterpret_cast<float4*>(g_acc1)[idx] = r;
}

// ---------------- final: h2 = relu(dis*(acc2+hs2)+b2); out = h2@Wc + bc ------
// One warp per node. lane handles features lane and lane+32.
__global__ void k_final(const float* __restrict__ b2, const float* __restrict__ Wc,
                        const float* __restrict__ bc, float* __restrict__ out)
{
    __shared__ float sWc[H2 * NC];
    __shared__ float sbc[NC];
    __shared__ float sb2[H2];
    for (int i = threadIdx.x; i < H2 * NC; i += blockDim.x) sWc[i] = Wc[i];
    for (int i = threadIdx.x; i < H2; i += blockDim.x) sb2[i] = b2[i];
    if (threadIdx.x < NC) sbc[threadIdx.x] = bc[threadIdx.x];
    __syncthreads();

    int gwarp = (blockIdx.x * blockDim.x + threadIdx.x) >> 5;
    int lane = threadIdx.x & 31;
    if (gwarp >= NNODES) return;
    float s = g_dis[gwarp];
    long base = (long)gwarp * H2;
    int f0 = lane, f1 = lane + 32;
    float h0 = fmaxf(s * (g_acc2[base + f0] + g_hs2[base + f0]) + sb2[f0], 0.f);
    float h1 = fmaxf(s * (g_acc2[base + f1] + g_hs2[base + f1]) + sb2[f1], 0.f);

    float p[NC];
    #pragma unroll
    for (int c = 0; c < NC; c++)
        p[c] = h0 * sWc[f0 * NC + c] + h1 * sWc[f1 * NC + c];
    #pragma unroll
    for (int c = 0; c < NC; c++) {
        float v = p[c];
        #pragma unroll
        for (int o = 16; o; o >>= 1) v += __shfl_xor_sync(0xFFFFFFFFu, v, o);
        if (lane == c) out[(long)gwarp * NC + c] = v + sbc[c];
    }
}

// ---------------- launch ------------------------------------------------------
extern "C" void kernel_launch(void* const* d_in, const int* in_sizes, int n_in,
                              void* d_out, int out_size)
{
    const float* x  = (const float*)d_in[0];
    const void*  ei = d_in[1];                 // edge_index: int32 or int64 (probed)
    const float* W1 = (const float*)d_in[2];
    const float* b1 = (const float*)d_in[3];
    const float* W2 = (const float*)d_in[4];
    const float* b2 = (const float*)d_in[5];
    const float* Wc = (const float*)d_in[6];
    const float* bc = (const float*)d_in[7];
    float* out = (float*)d_out;

    const int E = in_sizes[1] / 2;

    // device addresses of scratch globals (resolved once on first,
    // non-captured, correctness call)
    static float *p_hs1 = nullptr, *p_acc1 = nullptr, *p_hs2 = nullptr, *p_acc2 = nullptr;
    if (!p_hs1) {
        cudaGetSymbolAddress((void**)&p_hs1,  g_hs1);
        cudaGetSymbolAddress((void**)&p_acc1, g_acc1);
        cudaGetSymbolAddress((void**)&p_hs2,  g_hs2);
        cudaGetSymbolAddress((void**)&p_acc2, g_acc2);
    }

    // dtype probe + degree + normalization
    k_probe<<<1, 256>>>((const unsigned*)ei);
    k_init<<<4096, 256>>>();
    k_degree<<<(E + 255) / 256, 256>>>(ei, E);
    k_rsqrt<<<(NNODES + 255) / 256, 256>>>();

    // layer 1: hs1 = dis * (x @ W1)
    k_gemm_scale<128, 128, 8, 8, 8><<<(NNODES + 127) / 128, 256>>>(
        x, W1, p_hs1, NNODES, FIN, H1);

    k_scatter<<<(int)(((long)E * (H1 / 4) + 255) / 256), 256>>>(
        ei, p_hs1, p_acc1, E, H1 / 4);

    k_finish1<<<(NNODES * H1 / 4 + 255) / 256, 256>>>(b1);

    // layer 2: hs2 = dis * (h @ W2)   (h lives in g_acc1 after finish1)
    k_gemm_scale<128, 64, 8, 8, 4><<<(NNODES + 127) / 128, 256>>>(
        p_acc1, W2, p_hs2, NNODES, H1, H2);

    k_scatter<<<(int)(((long)E * (H2 / 4) + 255) / 256), 256>>>(
        ei, p_hs2, p_acc2, E, H2 / 4);

    // fused layer-2 finish + classifier
    k_final<<<(NNODES * 32 + 255) / 256, 256>>>(b2, Wc, bc, out);
}

// round 5
// speedup vs baseline: 1.3382x; 1.3382x over previous
#include <cuda_runtime.h>
#include <cuda_bf16.h>
#include <cstdint>

// Problem constants (fixed by the dataset)
#define NNODES 100000
#define FIN    500
#define H1     128
#define H2     64
#define NC     10
#define K1PAD  512

// ---------------- scratch (device globals; no allocs allowed) ----------------
__device__ __align__(16) float g_dis [NNODES];
__device__ __align__(16) float g_hs1 [NNODES * H1];
__device__ __align__(16) float g_acc1[NNODES * H1];
__device__ __align__(16) float g_hs2 [NNODES * H2];
__device__ __align__(16) float g_acc2[NNODES * H2];
__device__ __align__(16) __nv_bfloat16 g_W1t_hi[H1 * K1PAD]; // [n][k] transposed, padded
__device__ __align__(16) __nv_bfloat16 g_W1t_lo[H1 * K1PAD];
__device__ __align__(16) __nv_bfloat16 g_W2t_hi[H2 * H1];
__device__ __align__(16) __nv_bfloat16 g_W2t_lo[H2 * H1];
__device__ int g_is64;

__device__ __forceinline__ uint32_t smem_u32(const void* p) {
    uint32_t a;
    asm("{ .reg .u64 t; cvta.to.shared.u64 t, %1; cvt.u32.u64 %0, t; }" : "=r"(a) : "l"(p));
    return a;
}
__device__ __forceinline__ void ldm_x4(uint32_t* r, uint32_t addr) {
    asm volatile("ldmatrix.sync.aligned.m8n8.x4.shared.b16 {%0,%1,%2,%3}, [%4];"
        : "=r"(r[0]), "=r"(r[1]), "=r"(r[2]), "=r"(r[3]) : "r"(addr));
}
__device__ __forceinline__ void mma_bf16(float* c, const uint32_t* a, const uint32_t* b) {
    asm volatile("mma.sync.aligned.m16n8k16.row.col.f32.bf16.bf16.f32 "
        "{%0,%1,%2,%3}, {%4,%5,%6,%7}, {%8,%9}, {%0,%1,%2,%3};"
        : "+f"(c[0]), "+f"(c[1]), "+f"(c[2]), "+f"(c[3])
        : "r"(a[0]), "r"(a[1]), "r"(a[2]), "r"(a[3]), "r"(b[0]), "r"(b[1]));
}

// ---------------- probe: detect int64 vs int32 edge_index layout -------------
__global__ void k_probe(const unsigned* __restrict__ w) {
    __shared__ unsigned red[256];
    unsigned o = 0;
    for (int i = threadIdx.x; i < 1024; i += 256) o |= w[2 * i + 1];
    red[threadIdx.x] = o;
    __syncthreads();
    for (int s = 128; s; s >>= 1) {
        if (threadIdx.x < s) red[threadIdx.x] |= red[threadIdx.x + s];
        __syncthreads();
    }
    if (threadIdx.x == 0) g_is64 = (red[0] == 0u) ? 1 : 0;
}
__device__ __forceinline__ int eidx(const void* __restrict__ ei, long pos) {
    if (g_is64) return (int)((const long long*)ei)[pos];
    return ((const int*)ei)[pos];
}

// ---------------- init / degree / rsqrt --------------------------------------
__global__ void k_init() {
    int i = blockIdx.x * blockDim.x + threadIdx.x;
    int stride = gridDim.x * blockDim.x;
    for (int j = i; j < NNODES; j += stride) g_dis[j] = 1.0f;
    float4 z = make_float4(0.f, 0.f, 0.f, 0.f);
    const int n1 = NNODES * H1 / 4;
    for (int j = i; j < n1; j += stride) reinterpret_cast<float4*>(g_acc1)[j] = z;
    const int n2 = NNODES * H2 / 4;
    for (int j = i; j < n2; j += stride) reinterpret_cast<float4*>(g_acc2)[j] = z;
}
__global__ void k_degree(const void* __restrict__ ei, int E) {
    int i = blockIdx.x * blockDim.x + threadIdx.x;
    if (i < E) atomicAdd(&g_dis[eidx(ei, (long)E + i)], 1.0f);
}
__global__ void k_rsqrt() {
    int i = blockIdx.x * blockDim.x + threadIdx.x;
    if (i < NNODES) g_dis[i] = rsqrtf(g_dis[i]);
}

// ---------------- weight prep: transpose + bf16 split + pad ------------------
__global__ void k_prepW(const float* __restrict__ W1, const float* __restrict__ W2) {
    int i = blockIdx.x * blockDim.x + threadIdx.x;
    if (i < H1 * K1PAD) {
        int n = i / K1PAD, k = i % K1PAD;
        float v = (k < FIN) ? W1[(long)k * H1 + n] : 0.f;
        __nv_bfloat16 h = __float2bfloat16(v);
        g_W1t_hi[i] = h;
        g_W1t_lo[i] = __float2bfloat16(v - __bfloat162float(h));
    }
    int j = i - H1 * K1PAD;
    if (j >= 0 && j < H2 * H1) {
        int n = j / H1, k = j % H1;
        float v = W2[(long)k * H2 + n];
        __nv_bfloat16 h = __float2bfloat16(v);
        g_W2t_hi[j] = h;
        g_W2t_lo[j] = __float2bfloat16(v - __bfloat162float(h));
    }
}

// ---------------- HMMA split-bf16 GEMM: Cout = dis[row] * (A @ Bt^T) ---------
// A: [M, KREAL] fp32 row-major. Bh/Bl: [BN-col weights][KPAD] bf16 pre-split.
// Block tile 128 x BN, warp tile 64 x (BN/4), K chunk = 32 fp32.
// Products: hi*hi + hi*lo + lo*hi (lo*lo dropped, ~2^-18 relative).
template <int BN, int KREAL, int KPAD>
__global__ __launch_bounds__(256) void k_mm(
    const float* __restrict__ A, const __nv_bfloat16* __restrict__ Bh,
    const __nv_bfloat16* __restrict__ Bl, float* __restrict__ Cout, int M)
{
    constexpr int BM = 128, BK = 32, C = KPAD / BK;
    constexpr int WN = BN / 4;     // 32 or 16
    constexpr int NT = WN / 8;     // 4 or 2
    constexpr int MT = 4;          // 64/16
    constexpr int AST = 40;        // padded row stride in bf16 (80 bytes)

    __shared__ __align__(16) __nv_bfloat16 sAh[BM * AST];
    __shared__ __align__(16) __nv_bfloat16 sAl[BM * AST];
    __shared__ __align__(16) __nv_bfloat16 sBh[BN * AST];
    __shared__ __align__(16) __nv_bfloat16 sBl[BN * AST];

    const int tid = threadIdx.x, wid = tid >> 5, lane = tid & 31;
    const int wm = wid >> 2, wn = wid & 3;           // 2 x 4 warp grid
    const int rowBase = blockIdx.x * BM;

    const uint32_t uAh = smem_u32(sAh), uAl = smem_u32(sAl);
    const uint32_t uBh = smem_u32(sBh), uBl = smem_u32(sBl);

    float acc[MT][NT][4];
    #pragma unroll
    for (int m = 0; m < MT; m++)
        #pragma unroll
        for (int n = 0; n < NT; n++)
            #pragma unroll
            for (int j = 0; j < 4; j++) acc[m][n][j] = 0.f;

    // ---- staging registers ----
    float4 aReg[4];
    uint4  bReg[4];
    const int aRow = tid >> 1;                  // 2 threads per row
    const int aC4b = (tid & 1) * 4;             // float4 column base
    const int bRowBuf = tid;                    // 0..2*BN-1 valid
    const bool bAct = bRowBuf < 2 * BN;
    const int bN = bAct ? (bRowBuf < BN ? bRowBuf : bRowBuf - BN) : 0;

    auto loadG = [&](int c) {
        const int k0 = c * BK;
        #pragma unroll
        for (int i = 0; i < 4; i++) {
            int gcol = k0 + (aC4b + i) * 4;
            int grow = rowBase + aRow;
            float4 v = make_float4(0.f, 0.f, 0.f, 0.f);
            if (grow < M) {
                if (gcol + 4 <= KREAL) {
                    v = *reinterpret_cast<const float4*>(A + (long)grow * KREAL + gcol);
                } else if (gcol < KREAL) {
                    float t[4];
                    #pragma unroll
                    for (int u = 0; u < 4; u++)
                        t[u] = (gcol + u < KREAL) ? A[(long)grow * KREAL + gcol + u] : 0.f;
                    v = make_float4(t[0], t[1], t[2], t[3]);
                }
            }
            aReg[i] = v;
        }
        if (bAct) {
            const char* src = (const char*)(bRowBuf < BN ? Bh : Bl) +
                              (long)bN * (KPAD * 2) + (long)c * 64;
            #pragma unroll
            for (int u = 0; u < 4; u++)
                bReg[u] = *reinterpret_cast<const uint4*>(src + u * 16);
        }
    };
    auto storeS = [&]() {
        char* ah = (char*)sAh + aRow * 80 + aC4b * 8;
        char* al = (char*)sAl + aRow * 80 + aC4b * 8;
        #pragma unroll
        for (int i = 0; i < 4; i++) {
            float4 v = aReg[i];
            __nv_bfloat16 hx = __float2bfloat16(v.x), hy = __float2bfloat16(v.y);
            __nv_bfloat16 hz = __float2bfloat16(v.z), hw = __float2bfloat16(v.w);
            unsigned h0 = ((unsigned)__bfloat16_as_ushort(hy) << 16) | __bfloat16_as_ushort(hx);
            unsigned h1 = ((unsigned)__bfloat16_as_ushort(hw) << 16) | __bfloat16_as_ushort(hz);
            __nv_bfloat16 lx = __float2bfloat16(v.x - __bfloat162float(hx));
            __nv_bfloat16 ly = __float2bfloat16(v.y - __bfloat162float(hy));
            __nv_bfloat16 lz = __float2bfloat16(v.z - __bfloat162float(hz));
            __nv_bfloat16 lw = __float2bfloat16(v.w - __bfloat162float(hw));
            unsigned l0 = ((unsigned)__bfloat16_as_ushort(ly) << 16) | __bfloat16_as_ushort(lx);
            unsigned l1 = ((unsigned)__bfloat16_as_ushort(lw) << 16) | __bfloat16_as_ushort(lz);
            *reinterpret_cast<uint2*>(ah + i * 8) = make_uint2(h0, h1);
            *reinterpret_cast<uint2*>(al + i * 8) = make_uint2(l0, l1);
        }
        if (bAct) {
            char* d = (char*)(bRowBuf < BN ? sBh : sBl) + bN * 80;
            #pragma unroll
            for (int u = 0; u < 4; u++)
                *reinterpret_cast<uint4*>(d + u * 16) = bReg[u];
        }
    };

    // ldmatrix lane-address components (same pattern for A and B)
    const int lRow = ((lane >> 3) & 1) * 8 + (lane & 7);   // row within 16
    const int lKof = (lane >> 4) * 16;                     // byte offset: k half

    auto compute = [&]() {
        #pragma unroll
        for (int kk = 0; kk < 2; kk++) {
            uint32_t afH[MT][4], afL[MT][4], bfH[NT][2], bfL[NT][2];
            #pragma unroll
            for (int mt = 0; mt < MT; mt++) {
                uint32_t off = (uint32_t)((wm * 64 + mt * 16 + lRow) * 80 + kk * 32 + lKof);
                ldm_x4(afH[mt], uAh + off);
                ldm_x4(afL[mt], uAl + off);
            }
            #pragma unroll
            for (int np = 0; np < NT / 2; np++) {
                uint32_t off = (uint32_t)((wn * WN + np * 16 + lRow) * 80 + kk * 32 + lKof);
                uint32_t rH[4], rL[4];
                ldm_x4(rH, uBh + off);
                ldm_x4(rL, uBl + off);
                bfH[np * 2][0] = rH[0]; bfH[np * 2][1] = rH[2];
                bfH[np * 2 + 1][0] = rH[1]; bfH[np * 2 + 1][1] = rH[3];
                bfL[np * 2][0] = rL[0]; bfL[np * 2][1] = rL[2];
                bfL[np * 2 + 1][0] = rL[1]; bfL[np * 2 + 1][1] = rL[3];
            }
            #pragma unroll
            for (int mt = 0; mt < MT; mt++)
                #pragma unroll
                for (int nt = 0; nt < NT; nt++) {
                    mma_bf16(acc[mt][nt], afH[mt], bfH[nt]);
                    mma_bf16(acc[mt][nt], afH[mt], bfL[nt]);
                    mma_bf16(acc[mt][nt], afL[mt], bfH[nt]);
                }
        }
    };

    loadG(0);
    storeS();
    __syncthreads();
    for (int c = 0; c < C; c++) {
        if (c + 1 < C) loadG(c + 1);
        compute();
        __syncthreads();
        if (c + 1 < C) { storeS(); __syncthreads(); }
    }

    // epilogue: scale rows by g_dis, store fp32
    #pragma unroll
    for (int mt = 0; mt < MT; mt++) {
        int r0 = rowBase + wm * 64 + mt * 16 + (lane >> 2);
        int r1 = r0 + 8;
        float s0 = (r0 < M) ? g_dis[r0] : 0.f;
        float s1 = (r1 < M) ? g_dis[r1] : 0.f;
        #pragma unroll
        for (int nt = 0; nt < NT; nt++) {
            int col = wn * WN + nt * 8 + 2 * (lane & 3);
            if (r0 < M) {
                float2 v = make_float2(acc[mt][nt][0] * s0, acc[mt][nt][1] * s0);
                *reinterpret_cast<float2*>(Cout + (long)r0 * BN + col) = v;
            }
            if (r1 < M) {
                float2 v = make_float2(acc[mt][nt][2] * s1, acc[mt][nt][3] * s1);
                *reinterpret_cast<float2*>(Cout + (long)r1 * BN + col) = v;
            }
        }
    }
}

// ---------------- scatter: acc[dst] += hs[src], float4 vector RED -----------
__global__ void k_scatter(const void* __restrict__ ei,
                          const float* __restrict__ hs, float* __restrict__ acc,
                          int E, int Fq)
{
    long idx = (long)blockIdx.x * blockDim.x + threadIdx.x;
    long total = (long)E * Fq;
    if (idx >= total) return;
    int e = (int)(idx / Fq);
    int q = (int)(idx - (long)e * Fq);
    int s = eidx(ei, e);
    int d = eidx(ei, (long)E + e);
    float4 v = reinterpret_cast<const float4*>(hs)[(long)s * Fq + q];
    float* p = acc + ((long)d * Fq + q) * 4;
    asm volatile("red.global.add.v4.f32 [%0], {%1, %2, %3, %4};"
                 :: "l"(p), "f"(v.x), "f"(v.y), "f"(v.z), "f"(v.w) : "memory");
}

// ---------------- layer finish: h = relu(dis*(acc+hs)+b), in-place in acc ---
__global__ void k_finish1(const float* __restrict__ b1) {
    int idx = blockIdx.x * blockDim.x + threadIdx.x;
    const int total = NNODES * H1 / 4;
    if (idx >= total) return;
    const int fq = H1 / 4;
    int node = idx / fq;
    int q = idx - node * fq;
    float s = g_dis[node];
    float4 a = reinterpret_cast<const float4*>(g_acc1)[idx];
    float4 h = reinterpret_cast<const float4*>(g_hs1)[idx];
    float4 bb = reinterpret_cast<const float4*>(b1)[q];
    float4 r;
    r.x = fmaxf(s * (a.x + h.x) + bb.x, 0.f);
    r.y = fmaxf(s * (a.y + h.y) + bb.y, 0.f);
    r.z = fmaxf(s * (a.z + h.z) + bb.z, 0.f);
    r.w = fmaxf(s * (a.w + h.w) + bb.w, 0.f);
    reinterpret_cast<float4*>(g_acc1)[idx] = r;
}

// ---------------- final: h2 = relu(dis*(acc2+hs2)+b2); out = h2@Wc + bc ------
__global__ void k_final(const float* __restrict__ b2, const float* __restrict__ Wc,
                        const float* __restrict__ bc, float* __restrict__ out)
{
    __shared__ float sWc[H2 * NC];
    __shared__ float sbc[NC];
    __shared__ float sb2[H2];
    for (int i = threadIdx.x; i < H2 * NC; i += blockDim.x) sWc[i] = Wc[i];
    for (int i = threadIdx.x; i < H2; i += blockDim.x) sb2[i] = b2[i];
    if (threadIdx.x < NC) sbc[threadIdx.x] = bc[threadIdx.x];
    __syncthreads();

    int gwarp = (blockIdx.x * blockDim.x + threadIdx.x) >> 5;
    int lane = threadIdx.x & 31;
    if (gwarp >= NNODES) return;
    float s = g_dis[gwarp];
    long base = (long)gwarp * H2;
    int f0 = lane, f1 = lane + 32;
    float h0 = fmaxf(s * (g_acc2[base + f0] + g_hs2[base + f0]) + sb2[f0], 0.f);
    float h1 = fmaxf(s * (g_acc2[base + f1] + g_hs2[base + f1]) + sb2[f1], 0.f);

    float p[NC];
    #pragma unroll
    for (int c = 0; c < NC; c++)
        p[c] = h0 * sWc[f0 * NC + c] + h1 * sWc[f1 * NC + c];
    #pragma unroll
    for (int c = 0; c < NC; c++) {
        float v = p[c];
        #pragma unroll
        for (int o = 16; o; o >>= 1) v += __shfl_xor_sync(0xFFFFFFFFu, v, o);
        if (lane == c) out[(long)gwarp * NC + c] = v + sbc[c];
    }
}

// ---------------- launch ------------------------------------------------------
extern "C" void kernel_launch(void* const* d_in, const int* in_sizes, int n_in,
                              void* d_out, int out_size)
{
    const float* x  = (const float*)d_in[0];
    const void*  ei = d_in[1];
    const float* W1 = (const float*)d_in[2];
    const float* b1 = (const float*)d_in[3];
    const float* W2 = (const float*)d_in[4];
    const float* b2 = (const float*)d_in[5];
    const float* Wc = (const float*)d_in[6];
    const float* bc = (const float*)d_in[7];
    float* out = (float*)d_out;

    const int E = in_sizes[1] / 2;

    static float *p_hs1 = nullptr, *p_acc1 = nullptr, *p_hs2 = nullptr, *p_acc2 = nullptr;
    static __nv_bfloat16 *p_w1h = nullptr, *p_w1l = nullptr, *p_w2h = nullptr, *p_w2l = nullptr;
    if (!p_hs1) {
        cudaGetSymbolAddress((void**)&p_hs1,  g_hs1);
        cudaGetSymbolAddress((void**)&p_acc1, g_acc1);
        cudaGetSymbolAddress((void**)&p_hs2,  g_hs2);
        cudaGetSymbolAddress((void**)&p_acc2, g_acc2);
        cudaGetSymbolAddress((void**)&p_w1h,  g_W1t_hi);
        cudaGetSymbolAddress((void**)&p_w1l,  g_W1t_lo);
        cudaGetSymbolAddress((void**)&p_w2h,  g_W2t_hi);
        cudaGetSymbolAddress((void**)&p_w2l,  g_W2t_lo);
    }

    // prep: dtype probe, degree/norm, weight transpose+split
    k_probe<<<1, 256>>>((const unsigned*)ei);
    k_init<<<4096, 256>>>();
    k_degree<<<(E + 255) / 256, 256>>>(ei, E);
    k_rsqrt<<<(NNODES + 255) / 256, 256>>>();
    k_prepW<<<(H1 * K1PAD + H2 * H1 + 255) / 256, 256>>>(W1, W2);

    const int grid = (NNODES + 127) / 128;  // 782

    // layer 1: hs1 = dis * (x @ W1)   [HMMA split-bf16]
    k_mm<H1, FIN, K1PAD><<<grid, 256>>>(x, p_w1h, p_w1l, p_hs1, NNODES);

    k_scatter<<<(int)(((long)E * (H1 / 4) + 255) / 256), 256>>>(ei, p_hs1, p_acc1, E, H1 / 4);
    k_finish1<<<(NNODES * H1 / 4 + 255) / 256, 256>>>(b1);

    // layer 2: hs2 = dis * (h @ W2)
    k_mm<H2, H1, H1><<<grid, 256>>>(p_acc1, p_w2h, p_w2l, p_hs2, NNODES);

    k_scatter<<<(int)(((long)E * (H2 / 4) + 255) / 256), 256>>>(ei, p_hs2, p_acc2, E, H2 / 4);

    // fused layer-2 finish + classifier
    k_final<<<(NNODES * 32 + 255) / 256, 256>>>(b2, Wc, bc, out);
}

// round 6
// speedup vs baseline: 1.6829x; 1.2576x over previous
#include <cuda_runtime.h>
#include <cuda_bf16.h>
#include <cstdint>

// Problem constants (fixed by the dataset)
#define NNODES 100000
#define FIN    500
#define H1     128
#define H2     64
#define NC     10
#define K1PAD  512
#define EMAX   1700000
#define NB     391          // ceil(NNODES/256)

// ---------------- scratch (device globals; no allocs allowed) ----------------
__device__ __align__(16) float g_dis [NNODES];
__device__ __align__(16) float g_hs1 [NNODES * H1];
__device__ __align__(16) float g_acc1[NNODES * H1];
__device__ __align__(16) float g_hs2 [NNODES * H2];
__device__ __align__(16) __nv_bfloat16 g_W1t_hi[H1 * K1PAD];
__device__ __align__(16) __nv_bfloat16 g_W1t_lo[H1 * K1PAD];
__device__ __align__(16) __nv_bfloat16 g_W2t_hi[H2 * H1];
__device__ __align__(16) __nv_bfloat16 g_W2t_lo[H2 * H1];
__device__ int g_cnt   [NNODES];
__device__ int g_part  [512];
__device__ int g_rowptr[NNODES + 1];
__device__ int g_cursor[NNODES];
__device__ int g_col   [EMAX];
__device__ int g_is64;

__device__ __forceinline__ uint32_t smem_u32(const void* p) {
    uint32_t a;
    asm("{ .reg .u64 t; cvta.to.shared.u64 t, %1; cvt.u32.u64 %0, t; }" : "=r"(a) : "l"(p));
    return a;
}
__device__ __forceinline__ void ldm_x4(uint32_t* r, uint32_t addr) {
    asm volatile("ldmatrix.sync.aligned.m8n8.x4.shared.b16 {%0,%1,%2,%3}, [%4];"
        : "=r"(r[0]), "=r"(r[1]), "=r"(r[2]), "=r"(r[3]) : "r"(addr));
}
__device__ __forceinline__ void mma_bf16(float* c, const uint32_t* a, const uint32_t* b) {
    asm volatile("mma.sync.aligned.m16n8k16.row.col.f32.bf16.bf16.f32 "
        "{%0,%1,%2,%3}, {%4,%5,%6,%7}, {%8,%9}, {%0,%1,%2,%3};"
        : "+f"(c[0]), "+f"(c[1]), "+f"(c[2]), "+f"(c[3])
        : "r"(a[0]), "r"(a[1]), "r"(a[2]), "r"(a[3]), "r"(b[0]), "r"(b[1]));
}
__device__ __forceinline__ int eidx(const void* __restrict__ ei, long pos) {
    if (g_is64) return (int)((const long long*)ei)[pos];
    return ((const int*)ei)[pos];
}

// ---------- launch 1: probe dtype + zero histogram + weight split ------------
__global__ void k_probe_prep(const unsigned* __restrict__ w,
                             const float* __restrict__ W1,
                             const float* __restrict__ W2) {
    if (blockIdx.x == 0) {
        __shared__ unsigned red[256];
        unsigned o = 0;
        for (int i = threadIdx.x; i < 1024; i += 256) o |= w[2 * i + 1];
        red[threadIdx.x] = o;
        __syncthreads();
        for (int s = 128; s; s >>= 1) {
            if (threadIdx.x < s) red[threadIdx.x] |= red[threadIdx.x + s];
            __syncthreads();
        }
        if (threadIdx.x == 0) g_is64 = (red[0] == 0u) ? 1 : 0;
    }
    int i = blockIdx.x * blockDim.x + threadIdx.x;
    int stride = gridDim.x * blockDim.x;
    for (int j = i; j < NNODES; j += stride) g_cnt[j] = 0;
    for (int j = i; j < H1 * K1PAD; j += stride) {
        int n = j / K1PAD, k = j % K1PAD;
        float v = (k < FIN) ? W1[(long)k * H1 + n] : 0.f;
        __nv_bfloat16 h = __float2bfloat16(v);
        g_W1t_hi[j] = h;
        g_W1t_lo[j] = __float2bfloat16(v - __bfloat162float(h));
    }
    for (int j = i; j < H2 * H1; j += stride) {
        int n = j / H1, k = j % H1;
        float v = W2[(long)k * H2 + n];
        __nv_bfloat16 h = __float2bfloat16(v);
        g_W2t_hi[j] = h;
        g_W2t_lo[j] = __float2bfloat16(v - __bfloat162float(h));
    }
}

// ---------- launch 2: degree histogram --------------------------------------
__global__ void k_degree(const void* __restrict__ ei, int E) {
    int i = blockIdx.x * blockDim.x + threadIdx.x;
    if (i < E) atomicAdd(&g_cnt[eidx(ei, (long)E + i)], 1);
}

// ---------- launch 3: block sums + dis = rsqrt(cnt+1) ------------------------
__global__ void k_scanA() {
    int i = blockIdx.x * 256 + threadIdx.x;
    int v = (i < NNODES) ? g_cnt[i] : 0;
    if (i < NNODES) g_dis[i] = rsqrtf((float)v + 1.0f);
    __shared__ int s[256];
    s[threadIdx.x] = v;
    __syncthreads();
    for (int o = 128; o; o >>= 1) {
        if (threadIdx.x < o) s[threadIdx.x] += s[threadIdx.x + o];
        __syncthreads();
    }
    if (threadIdx.x == 0) g_part[blockIdx.x] = s[0];
}

// ---------- launch 5: scan the 391 block partials (exclusive) ----------------
__global__ void k_scanB() {
    __shared__ int s[512];
    int t = threadIdx.x;
    int v = (t < NB) ? g_part[t] : 0;
    s[t] = v;
    __syncthreads();
    for (int o = 1; o < 512; o <<= 1) {
        int x = (t >= o) ? s[t - o] : 0;
        __syncthreads();
        s[t] += x;
        __syncthreads();
    }
    if (t < NB) g_part[t] = s[t] - v;
}

// ---------- launch 6: per-element exclusive scan -> rowptr + cursor ----------
__global__ void k_scanC() {
    int b = blockIdx.x, t = threadIdx.x, i = b * 256 + t;
    int v = (i < NNODES) ? g_cnt[i] : 0;
    __shared__ int s[256];
    s[t] = v;
    __syncthreads();
    for (int o = 1; o < 256; o <<= 1) {
        int x = (t >= o) ? s[t - o] : 0;
        __syncthreads();
        s[t] += x;
        __syncthreads();
    }
    int excl = g_part[b] + s[t] - v;
    if (i < NNODES) {
        g_rowptr[i] = excl;
        g_cursor[i] = excl;
        if (i == NNODES - 1) g_rowptr[NNODES] = excl + v;
    }
}

// ---------- launch 7: CSR fill (col = src grouped by dst) --------------------
__global__ void k_fill(const void* __restrict__ ei, int E) {
    int i = blockIdx.x * blockDim.x + threadIdx.x;
    if (i < E) {
        int s = eidx(ei, i);
        int d = eidx(ei, (long)E + i);
        int pos = atomicAdd(&g_cursor[d], 1);
        g_col[pos] = s;
    }
}

// ---------------- HMMA split-bf16 GEMM: Cout = dis[row] * (A @ Bt^T) ---------
template <int BN, int KREAL, int KPAD>
__global__ __launch_bounds__(256) void k_mm(
    const float* __restrict__ A, const __nv_bfloat16* __restrict__ Bh,
    const __nv_bfloat16* __restrict__ Bl, float* __restrict__ Cout, int M)
{
    constexpr int BM = 128, BK = 32, C = KPAD / BK;
    constexpr int WN = BN / 4;
    constexpr int NT = WN / 8;
    constexpr int MT = 4;
    constexpr int AST = 40;

    __shared__ __align__(16) __nv_bfloat16 sAh[BM * AST];
    __shared__ __align__(16) __nv_bfloat16 sAl[BM * AST];
    __shared__ __align__(16) __nv_bfloat16 sBh[BN * AST];
    __shared__ __align__(16) __nv_bfloat16 sBl[BN * AST];

    const int tid = threadIdx.x, wid = tid >> 5, lane = tid & 31;
    const int wm = wid >> 2, wn = wid & 3;
    const int rowBase = blockIdx.x * BM;

    const uint32_t uAh = smem_u32(sAh), uAl = smem_u32(sAl);
    const uint32_t uBh = smem_u32(sBh), uBl = smem_u32(sBl);

    float acc[MT][NT][4];
    #pragma unroll
    for (int m = 0; m < MT; m++)
        #pragma unroll
        for (int n = 0; n < NT; n++)
            #pragma unroll
            for (int j = 0; j < 4; j++) acc[m][n][j] = 0.f;

    float4 aReg[4];
    uint4  bReg[4];
    const int aRow = tid >> 1;
    const int aC4b = (tid & 1) * 4;
    const int bRowBuf = tid;
    const bool bAct = bRowBuf < 2 * BN;
    const int bN = bAct ? (bRowBuf < BN ? bRowBuf : bRowBuf - BN) : 0;

    auto loadG = [&](int c) {
        const int k0 = c * BK;
        #pragma unroll
        for (int i = 0; i < 4; i++) {
            int gcol = k0 + (aC4b + i) * 4;
            int grow = rowBase + aRow;
            float4 v = make_float4(0.f, 0.f, 0.f, 0.f);
            if (grow < M) {
                if (gcol + 4 <= KREAL) {
                    v = *reinterpret_cast<const float4*>(A + (long)grow * KREAL + gcol);
                } else if (gcol < KREAL) {
                    float t[4];
                    #pragma unroll
                    for (int u = 0; u < 4; u++)
                        t[u] = (gcol + u < KREAL) ? A[(long)grow * KREAL + gcol + u] : 0.f;
                    v = make_float4(t[0], t[1], t[2], t[3]);
                }
            }
            aReg[i] = v;
        }
        if (bAct) {
            const char* src = (const char*)(bRowBuf < BN ? Bh : Bl) +
                              (long)bN * (KPAD * 2) + (long)c * 64;
            #pragma unroll
            for (int u = 0; u < 4; u++)
                bReg[u] = *reinterpret_cast<const uint4*>(src + u * 16);
        }
    };
    auto storeS = [&]() {
        char* ah = (char*)sAh + aRow * 80 + aC4b * 8;
        char* al = (char*)sAl + aRow * 80 + aC4b * 8;
        #pragma unroll
        for (int i = 0; i < 4; i++) {
            float4 v = aReg[i];
            __nv_bfloat16 hx = __float2bfloat16(v.x), hy = __float2bfloat16(v.y);
            __nv_bfloat16 hz = __float2bfloat16(v.z), hw = __float2bfloat16(v.w);
            unsigned h0 = ((unsigned)__bfloat16_as_ushort(hy) << 16) | __bfloat16_as_ushort(hx);
            unsigned h1 = ((unsigned)__bfloat16_as_ushort(hw) << 16) | __bfloat16_as_ushort(hz);
            __nv_bfloat16 lx = __float2bfloat16(v.x - __bfloat162float(hx));
            __nv_bfloat16 ly = __float2bfloat16(v.y - __bfloat162float(hy));
            __nv_bfloat16 lz = __float2bfloat16(v.z - __bfloat162float(hz));
            __nv_bfloat16 lw = __float2bfloat16(v.w - __bfloat162float(hw));
            unsigned l0 = ((unsigned)__bfloat16_as_ushort(ly) << 16) | __bfloat16_as_ushort(lx);
            unsigned l1 = ((unsigned)__bfloat16_as_ushort(lw) << 16) | __bfloat16_as_ushort(lz);
            *reinterpret_cast<uint2*>(ah + i * 8) = make_uint2(h0, h1);
            *reinterpret_cast<uint2*>(al + i * 8) = make_uint2(l0, l1);
        }
        if (bAct) {
            char* d = (char*)(bRowBuf < BN ? sBh : sBl) + bN * 80;
            #pragma unroll
            for (int u = 0; u < 4; u++)
                *reinterpret_cast<uint4*>(d + u * 16) = bReg[u];
        }
    };

    const int lRow = ((lane >> 3) & 1) * 8 + (lane & 7);
    const int lKof = (lane >> 4) * 16;

    auto compute = [&]() {
        #pragma unroll
        for (int kk = 0; kk < 2; kk++) {
            uint32_t afH[MT][4], afL[MT][4], bfH[NT][2], bfL[NT][2];
            #pragma unroll
            for (int mt = 0; mt < MT; mt++) {
                uint32_t off = (uint32_t)((wm * 64 + mt * 16 + lRow) * 80 + kk * 32 + lKof);
                ldm_x4(afH[mt], uAh + off);
                ldm_x4(afL[mt], uAl + off);
            }
            #pragma unroll
            for (int np = 0; np < NT / 2; np++) {
                uint32_t off = (uint32_t)((wn * WN + np * 16 + lRow) * 80 + kk * 32 + lKof);
                uint32_t rH[4], rL[4];
                ldm_x4(rH, uBh + off);
                ldm_x4(rL, uBl + off);
                bfH[np * 2][0] = rH[0]; bfH[np * 2][1] = rH[2];
                bfH[np * 2 + 1][0] = rH[1]; bfH[np * 2 + 1][1] = rH[3];
                bfL[np * 2][0] = rL[0]; bfL[np * 2][1] = rL[2];
                bfL[np * 2 + 1][0] = rL[1]; bfL[np * 2 + 1][1] = rL[3];
            }
            #pragma unroll
            for (int mt = 0; mt < MT; mt++)
                #pragma unroll
                for (int nt = 0; nt < NT; nt++) {
                    mma_bf16(acc[mt][nt], afH[mt], bfH[nt]);
                    mma_bf16(acc[mt][nt], afH[mt], bfL[nt]);
                    mma_bf16(acc[mt][nt], afL[mt], bfH[nt]);
                }
        }
    };

    loadG(0);
    storeS();
    __syncthreads();
    for (int c = 0; c < C; c++) {
        if (c + 1 < C) loadG(c + 1);
        compute();
        __syncthreads();
        if (c + 1 < C) { storeS(); __syncthreads(); }
    }

    #pragma unroll
    for (int mt = 0; mt < MT; mt++) {
        int r0 = rowBase + wm * 64 + mt * 16 + (lane >> 2);
        int r1 = r0 + 8;
        float s0 = (r0 < M) ? g_dis[r0] : 0.f;
        float s1 = (r1 < M) ? g_dis[r1] : 0.f;
        #pragma unroll
        for (int nt = 0; nt < NT; nt++) {
            int col = wn * WN + nt * 8 + 2 * (lane & 3);
            if (r0 < M) {
                float2 v = make_float2(acc[mt][nt][0] * s0, acc[mt][nt][1] * s0);
                *reinterpret_cast<float2*>(Cout + (long)r0 * BN + col) = v;
            }
            if (r1 < M) {
                float2 v = make_float2(acc[mt][nt][2] * s1, acc[mt][nt][3] * s1);
                *reinterpret_cast<float2*>(Cout + (long)r1 * BN + col) = v;
            }
        }
    }
}

// ---------- launch 8: CSR aggregation layer1 + finish (block = node) ---------
__global__ __launch_bounds__(128) void k_agg1(const float* __restrict__ b1) {
    const int n = blockIdx.x, t = threadIdx.x;
    const int s0 = g_rowptr[n], e0 = g_rowptr[n + 1];
    float a0 = 0.f, a1 = 0.f, a2 = 0.f, a3 = 0.f;
    int i = s0;
    for (; i + 4 <= e0; i += 4) {
        int c0 = g_col[i], c1 = g_col[i + 1], c2 = g_col[i + 2], c3 = g_col[i + 3];
        a0 += g_hs1[(long)c0 * H1 + t];
        a1 += g_hs1[(long)c1 * H1 + t];
        a2 += g_hs1[(long)c2 * H1 + t];
        a3 += g_hs1[(long)c3 * H1 + t];
    }
    for (; i < e0; i++) a0 += g_hs1[(long)g_col[i] * H1 + t];
    float a = (a0 + a1) + (a2 + a3);
    float h = fmaxf(g_dis[n] * (a + g_hs1[(long)n * H1 + t]) + __ldg(&b1[t]), 0.f);
    g_acc1[(long)n * H1 + t] = h;
}

// ---------- launch 10: CSR aggregation layer2 + finish + classifier ----------
__global__ __launch_bounds__(64) void k_agg2(
    const float* __restrict__ b2, const float* __restrict__ Wc,
    const float* __restrict__ bc, float* __restrict__ out) {
    const int n = blockIdx.x, t = threadIdx.x;
    const int s0 = g_rowptr[n], e0 = g_rowptr[n + 1];
    float a0 = 0.f, a1 = 0.f, a2 = 0.f, a3 = 0.f;
    int i = s0;
    for (; i + 4 <= e0; i += 4) {
        int c0 = g_col[i], c1 = g_col[i + 1], c2 = g_col[i + 2], c3 = g_col[i + 3];
        a0 += g_hs2[(long)c0 * H2 + t];
        a1 += g_hs2[(long)c1 * H2 + t];
        a2 += g_hs2[(long)c2 * H2 + t];
        a3 += g_hs2[(long)c3 * H2 + t];
    }
    for (; i < e0; i++) a0 += g_hs2[(long)g_col[i] * H2 + t];
    float a = (a0 + a1) + (a2 + a3);
    float h = fmaxf(g_dis[n] * (a + g_hs2[(long)n * H2 + t]) + __ldg(&b2[t]), 0.f);

    const int lane = t & 31, w = t >> 5;
    __shared__ float sred[NC];
    float p[NC];
    #pragma unroll
    for (int c = 0; c < NC; c++) {
        float v = h * __ldg(&Wc[t * NC + c]);
        #pragma unroll
        for (int o = 16; o; o >>= 1) v += __shfl_xor_sync(0xFFFFFFFFu, v, o);
        p[c] = v;
    }
    if (w == 1 && lane == 0) {
        #pragma unroll
        for (int c = 0; c < NC; c++) sred[c] = p[c];
    }
    __syncthreads();
    if (w == 0 && lane == 0) {
        #pragma unroll
        for (int c = 0; c < NC; c++)
            out[(long)n * NC + c] = p[c] + sred[c] + __ldg(&bc[c]);
    }
}

// ---------------- launch ------------------------------------------------------
extern "C" void kernel_launch(void* const* d_in, const int* in_sizes, int n_in,
                              void* d_out, int out_size)
{
    const float* x  = (const float*)d_in[0];
    const void*  ei = d_in[1];
    const float* W1 = (const float*)d_in[2];
    const float* b1 = (const float*)d_in[3];
    const float* W2 = (const float*)d_in[4];
    const float* b2 = (const float*)d_in[5];
    const float* Wc = (const float*)d_in[6];
    const float* bc = (const float*)d_in[7];
    float* out = (float*)d_out;

    const int E = in_sizes[1] / 2;

    static float *p_hs1 = nullptr, *p_acc1 = nullptr, *p_hs2 = nullptr;
    static __nv_bfloat16 *p_w1h = nullptr, *p_w1l = nullptr, *p_w2h = nullptr, *p_w2l = nullptr;
    if (!p_hs1) {
        cudaGetSymbolAddress((void**)&p_hs1,  g_hs1);
        cudaGetSymbolAddress((void**)&p_acc1, g_acc1);
        cudaGetSymbolAddress((void**)&p_hs2,  g_hs2);
        cudaGetSymbolAddress((void**)&p_w1h,  g_W1t_hi);
        cudaGetSymbolAddress((void**)&p_w1l,  g_W1t_lo);
        cudaGetSymbolAddress((void**)&p_w2h,  g_W2t_hi);
        cudaGetSymbolAddress((void**)&p_w2l,  g_W2t_lo);
    }

    const int grid = (NNODES + 127) / 128;  // 782

    // 1: probe + zero hist + weight split
    k_probe_prep<<<512, 256>>>((const unsigned*)ei, W1, W2);
    // 2: degree histogram
    k_degree<<<(E + 255) / 256, 256>>>(ei, E);
    // 3: block sums + dis
    k_scanA<<<NB, 256>>>();
    // 4: layer-1 GEMM  (lands in the ncu -s 5 -c 1 window)
    k_mm<H1, FIN, K1PAD><<<grid, 256>>>(x, p_w1h, p_w1l, p_hs1, NNODES);
    // 5-7: finish CSR build
    k_scanB<<<1, 512>>>();
    k_scanC<<<NB, 256>>>();
    k_fill<<<(E + 255) / 256, 256>>>(ei, E);
    // 8: layer-1 aggregation + relu (writes h into acc1)
    k_agg1<<<NNODES, 128>>>(b1);
    // 9: layer-2 GEMM
    k_mm<H2, H1, H1><<<grid, 256>>>(p_acc1, p_w2h, p_w2l, p_hs2, NNODES);
    // 10: layer-2 aggregation + relu + classifier
    k_agg2<<<NNODES, 64>>>(b2, Wc, bc, out);
}

// round 7
// speedup vs baseline: 1.9479x; 1.1574x over previous
#include <cuda_runtime.h>
#include <cuda_bf16.h>
#include <cstdint>

// Problem constants (fixed by the dataset)
#define NNODES 100000
#define FIN    500
#define H1     128
#define H2     64
#define NC     10
#define K1PAD  512
#define EMAX   1700000
#define NB     391          // ceil(NNODES/256)

// ---------------- scratch (device globals; no allocs allowed) ----------------
__device__ __align__(16) float g_dis [NNODES];
__device__ __align__(16) float g_hs1 [NNODES * H1];
__device__ __align__(16) float g_acc1[NNODES * H1];
__device__ __align__(16) float g_hs2 [NNODES * H2];
__device__ __align__(16) __nv_bfloat16 g_W1t_hi[H1 * K1PAD];
__device__ __align__(16) __nv_bfloat16 g_W1t_lo[H1 * K1PAD];
__device__ __align__(16) __nv_bfloat16 g_W2t_hi[H2 * H1];
__device__ __align__(16) __nv_bfloat16 g_W2t_lo[H2 * H1];
__device__ int g_cnt   [NNODES];
__device__ int g_part  [512];
__device__ int g_rowptr[NNODES + 1];
__device__ int g_cursor[NNODES];
__device__ int g_col   [EMAX];
__device__ int g_is64;

__device__ __forceinline__ uint32_t smem_u32(const void* p) {
    uint32_t a;
    asm("{ .reg .u64 t; cvta.to.shared.u64 t, %1; cvt.u32.u64 %0, t; }" : "=r"(a) : "l"(p));
    return a;
}
__device__ __forceinline__ void ldm_x4(uint32_t* r, uint32_t addr) {
    asm volatile("ldmatrix.sync.aligned.m8n8.x4.shared.b16 {%0,%1,%2,%3}, [%4];"
        : "=r"(r[0]), "=r"(r[1]), "=r"(r[2]), "=r"(r[3]) : "r"(addr));
}
__device__ __forceinline__ void mma_bf16(float* c, const uint32_t* a, const uint32_t* b) {
    asm volatile("mma.sync.aligned.m16n8k16.row.col.f32.bf16.bf16.f32 "
        "{%0,%1,%2,%3}, {%4,%5,%6,%7}, {%8,%9}, {%0,%1,%2,%3};"
        : "+f"(c[0]), "+f"(c[1]), "+f"(c[2]), "+f"(c[3])
        : "r"(a[0]), "r"(a[1]), "r"(a[2]), "r"(a[3]), "r"(b[0]), "r"(b[1]));
}
__device__ __forceinline__ void cp16(uint32_t dst, const void* src) {
    asm volatile("cp.async.cg.shared.global [%0], [%1], 16;" :: "r"(dst), "l"(src));
}
__device__ __forceinline__ int eidx(const void* __restrict__ ei, long pos) {
    if (g_is64) return (int)((const long long*)ei)[pos];
    return ((const int*)ei)[pos];
}

// ---------- launch 1: probe dtype + zero histogram + weight split ------------
__global__ void k_probe_prep(const unsigned* __restrict__ w,
                             const float* __restrict__ W1,
                             const float* __restrict__ W2) {
    if (blockIdx.x == 0) {
        __shared__ unsigned red[256];
        unsigned o = 0;
        for (int i = threadIdx.x; i < 1024; i += 256) o |= w[2 * i + 1];
        red[threadIdx.x] = o;
        __syncthreads();
        for (int s = 128; s; s >>= 1) {
            if (threadIdx.x < s) red[threadIdx.x] |= red[threadIdx.x + s];
            __syncthreads();
        }
        if (threadIdx.x == 0) g_is64 = (red[0] == 0u) ? 1 : 0;
    }
    int i = blockIdx.x * blockDim.x + threadIdx.x;
    int stride = gridDim.x * blockDim.x;
    for (int j = i; j < NNODES; j += stride) g_cnt[j] = 0;
    for (int j = i; j < H1 * K1PAD; j += stride) {
        int n = j / K1PAD, k = j % K1PAD;
        float v = (k < FIN) ? W1[(long)k * H1 + n] : 0.f;
        __nv_bfloat16 h = __float2bfloat16(v);
        g_W1t_hi[j] = h;
        g_W1t_lo[j] = __float2bfloat16(v - __bfloat162float(h));
    }
    for (int j = i; j < H2 * H1; j += stride) {
        int n = j / H1, k = j % H1;
        float v = W2[(long)k * H2 + n];
        __nv_bfloat16 h = __float2bfloat16(v);
        g_W2t_hi[j] = h;
        g_W2t_lo[j] = __float2bfloat16(v - __bfloat162float(h));
    }
}

// ---------- launch 2: degree histogram --------------------------------------
__global__ void k_degree(const void* __restrict__ ei, int E) {
    int i = blockIdx.x * blockDim.x + threadIdx.x;
    if (i < E) atomicAdd(&g_cnt[eidx(ei, (long)E + i)], 1);
}

// ---------- launch 3: block sums + dis = rsqrt(cnt+1) ------------------------
__global__ void k_scanA() {
    int i = blockIdx.x * 256 + threadIdx.x;
    int v = (i < NNODES) ? g_cnt[i] : 0;
    if (i < NNODES) g_dis[i] = rsqrtf((float)v + 1.0f);
    __shared__ int s[256];
    s[threadIdx.x] = v;
    __syncthreads();
    for (int o = 128; o; o >>= 1) {
        if (threadIdx.x < o) s[threadIdx.x] += s[threadIdx.x + o];
        __syncthreads();
    }
    if (threadIdx.x == 0) g_part[blockIdx.x] = s[0];
}

// ---------- launch 5: scan the 391 block partials (exclusive) ----------------
__global__ void k_scanB() {
    __shared__ int s[512];
    int t = threadIdx.x;
    int v = (t < NB) ? g_part[t] : 0;
    s[t] = v;
    __syncthreads();
    for (int o = 1; o < 512; o <<= 1) {
        int x = (t >= o) ? s[t - o] : 0;
        __syncthreads();
        s[t] += x;
        __syncthreads();
    }
    if (t < NB) g_part[t] = s[t] - v;
}

// ---------- launch 6: per-element exclusive scan -> rowptr + cursor ----------
__global__ void k_scanC() {
    int b = blockIdx.x, t = threadIdx.x, i = b * 256 + t;
    int v = (i < NNODES) ? g_cnt[i] : 0;
    __shared__ int s[256];
    s[t] = v;
    __syncthreads();
    for (int o = 1; o < 256; o <<= 1) {
        int x = (t >= o) ? s[t - o] : 0;
        __syncthreads();
        s[t] += x;
        __syncthreads();
    }
    int excl = g_part[b] + s[t] - v;
    if (i < NNODES) {
        g_rowptr[i] = excl;
        g_cursor[i] = excl;
        if (i == NNODES - 1) g_rowptr[NNODES] = excl + v;
    }
}

// ---------- launch 7: CSR fill (col = src grouped by dst) --------------------
__global__ void k_fill(const void* __restrict__ ei, int E) {
    int i = blockIdx.x * blockDim.x + threadIdx.x;
    if (i < E) {
        int s = eidx(ei, i);
        int d = eidx(ei, (long)E + i);
        int pos = atomicAdd(&g_cursor[d], 1);
        g_col[pos] = s;
    }
}

// ---------------- HMMA split-bf16 GEMM: Cout = dis[row] * (A @ Bt^T) ---------
// 2 CTAs/SM, double-buffered SMEM, cp.async for B (pre-split bf16 weights),
// register-staged fp32->bf16 hi/lo conversion for A.
template <int BN, int KREAL, int KPAD>
__global__ __launch_bounds__(256, 2) void k_mm(
    const float* __restrict__ A, const __nv_bfloat16* __restrict__ Bh,
    const __nv_bfloat16* __restrict__ Bl, float* __restrict__ Cout, int M)
{
    constexpr int BM = 128, BK = 32, C = KPAD / BK;
    constexpr int WN = BN / 4;
    constexpr int NT = WN / 8;
    constexpr int MT = 4;
    constexpr int ROWB = 80;                       // 40 bf16, conflict-free stride
    constexpr int STG = (2 * BM + 2 * BN) * ROWB;  // bytes per stage
    constexpr uint32_t oAl = BM * ROWB;
    constexpr uint32_t oBh = 2 * BM * ROWB;
    constexpr uint32_t oBl = 2 * BM * ROWB + BN * ROWB;

    extern __shared__ char sm[];
    const uint32_t u0 = smem_u32(sm);

    const int tid = threadIdx.x, wid = tid >> 5, lane = tid & 31;
    const int wm = wid >> 2, wn = wid & 3;
    const int rowBase = blockIdx.x * BM;

    float acc[MT][NT][4];
    #pragma unroll
    for (int m = 0; m < MT; m++)
        #pragma unroll
        for (int n = 0; n < NT; n++)
            #pragma unroll
            for (int j = 0; j < 4; j++) acc[m][n][j] = 0.f;

    float4 aReg[4];
    const int aRow = tid >> 1;
    const int aC4b = (tid & 1) * 4;

    auto loadA = [&](int c) {
        const int k0 = c * BK;
        const int grow = rowBase + aRow;
        #pragma unroll
        for (int i = 0; i < 4; i++) {
            int gcol = k0 + (aC4b + i) * 4;
            float4 v = make_float4(0.f, 0.f, 0.f, 0.f);
            if (grow < M) {
                if (gcol + 4 <= KREAL) {
                    v = *reinterpret_cast<const float4*>(A + (long)grow * KREAL + gcol);
                } else if (gcol < KREAL) {
                    float t[4];
                    #pragma unroll
                    for (int u = 0; u < 4; u++)
                        t[u] = (gcol + u < KREAL) ? A[(long)grow * KREAL + gcol + u] : 0.f;
                    v = make_float4(t[0], t[1], t[2], t[3]);
                }
            }
            aReg[i] = v;
        }
    };
    auto storeA = [&](int s) {
        char* ah = sm + s * STG + aRow * ROWB + aC4b * 8;
        char* al = ah + oAl;
        #pragma unroll
        for (int i = 0; i < 4; i++) {
            float4 v = aReg[i];
            __nv_bfloat16 hx = __float2bfloat16(v.x), hy = __float2bfloat16(v.y);
            __nv_bfloat16 hz = __float2bfloat16(v.z), hw = __float2bfloat16(v.w);
            unsigned h0 = ((unsigned)__bfloat16_as_ushort(hy) << 16) | __bfloat16_as_ushort(hx);
            unsigned h1 = ((unsigned)__bfloat16_as_ushort(hw) << 16) | __bfloat16_as_ushort(hz);
            __nv_bfloat16 lx = __float2bfloat16(v.x - __bfloat162float(hx));
            __nv_bfloat16 ly = __float2bfloat16(v.y - __bfloat162float(hy));
            __nv_bfloat16 lz = __float2bfloat16(v.z - __bfloat162float(hz));
            __nv_bfloat16 lw = __float2bfloat16(v.w - __bfloat162float(hw));
            unsigned l0 = ((unsigned)__bfloat16_as_ushort(ly) << 16) | __bfloat16_as_ushort(lx);
            unsigned l1 = ((unsigned)__bfloat16_as_ushort(lw) << 16) | __bfloat16_as_ushort(lz);
            *reinterpret_cast<uint2*>(ah + i * 8) = make_uint2(h0, h1);
            *reinterpret_cast<uint2*>(al + i * 8) = make_uint2(l0, l1);
        }
    };
    auto cpB = [&](int c, int s) {
        #pragma unroll
        for (int i = tid; i < BN * 8; i += 256) {
            int mat = (i >= BN * 4) ? 1 : 0;
            int j = i - mat * BN * 4;
            int row = j >> 2, u = j & 3;
            const char* src = (const char*)(mat ? Bl : Bh) +
                              (long)row * (KPAD * 2) + (long)c * 64 + u * 16;
            uint32_t dst = u0 + s * STG + (mat ? oBl : oBh) + row * ROWB + u * 16;
            cp16(dst, src);
        }
    };

    const int lRow = ((lane >> 3) & 1) * 8 + (lane & 7);
    const int lKof = (lane >> 4) * 16;

    auto compute = [&](int s) {
        const uint32_t base = u0 + s * STG;
        #pragma unroll
        for (int kk = 0; kk < 2; kk++) {
            uint32_t bfH[NT][2], bfL[NT][2];
            #pragma unroll
            for (int np = 0; np < NT / 2; np++) {
                uint32_t off = base + oBh + (uint32_t)((wn * WN + np * 16 + lRow) * ROWB + kk * 32 + lKof);
                uint32_t rH[4], rL[4];
                ldm_x4(rH, off);
                ldm_x4(rL, off + (oBl - oBh));
                bfH[np * 2][0] = rH[0]; bfH[np * 2][1] = rH[2];
                bfH[np * 2 + 1][0] = rH[1]; bfH[np * 2 + 1][1] = rH[3];
                bfL[np * 2][0] = rL[0]; bfL[np * 2][1] = rL[2];
                bfL[np * 2 + 1][0] = rL[1]; bfL[np * 2 + 1][1] = rL[3];
            }
            #pragma unroll
            for (int mt = 0; mt < MT; mt++) {
                uint32_t off = base + (uint32_t)((wm * 64 + mt * 16 + lRow) * ROWB + kk * 32 + lKof);
                uint32_t afH[4], afL[4];
                ldm_x4(afH, off);
                ldm_x4(afL, off + oAl);
                #pragma unroll
                for (int nt = 0; nt < NT; nt++) {
                    mma_bf16(acc[mt][nt], afH, bfH[nt]);
                    mma_bf16(acc[mt][nt], afH, bfL[nt]);
                    mma_bf16(acc[mt][nt], afL, bfH[nt]);
                }
            }
        }
    };

    // prologue: chunk 0 into stage 0
    loadA(0);
    cpB(0, 0);
    storeA(0);
    asm volatile("cp.async.commit_group;");
    asm volatile("cp.async.wait_group 0;");
    __syncthreads();

    for (int c = 0; c < C; c++) {
        const int s = c & 1;
        if (c + 1 < C) {
            loadA(c + 1);
            cpB(c + 1, s ^ 1);
            asm volatile("cp.async.commit_group;");
        }
        compute(s);
        if (c + 1 < C) {
            storeA(s ^ 1);
            asm volatile("cp.async.wait_group 0;");
            __syncthreads();
        }
    }

    #pragma unroll
    for (int mt = 0; mt < MT; mt++) {
        int r0 = rowBase + wm * 64 + mt * 16 + (lane >> 2);
        int r1 = r0 + 8;
        float s0 = (r0 < M) ? g_dis[r0] : 0.f;
        float s1 = (r1 < M) ? g_dis[r1] : 0.f;
        #pragma unroll
        for (int nt = 0; nt < NT; nt++) {
            int col = wn * WN + nt * 8 + 2 * (lane & 3);
            if (r0 < M) {
                float2 v = make_float2(acc[mt][nt][0] * s0, acc[mt][nt][1] * s0);
                *reinterpret_cast<float2*>(Cout + (long)r0 * BN + col) = v;
            }
            if (r1 < M) {
                float2 v = make_float2(acc[mt][nt][2] * s1, acc[mt][nt][3] * s1);
                *reinterpret_cast<float2*>(Cout + (long)r1 * BN + col) = v;
            }
        }
    }
}

// ---------- CSR aggregation layer1 + finish (block = node) -------------------
__global__ __launch_bounds__(128) void k_agg1(const float* __restrict__ b1) {
    const int n = blockIdx.x, t = threadIdx.x;
    const int s0 = g_rowptr[n], e0 = g_rowptr[n + 1];
    float a0 = 0.f, a1 = 0.f, a2 = 0.f, a3 = 0.f;
    int i = s0;
    for (; i + 4 <= e0; i += 4) {
        int c0 = g_col[i], c1 = g_col[i + 1], c2 = g_col[i + 2], c3 = g_col[i + 3];
        a0 += g_hs1[(long)c0 * H1 + t];
        a1 += g_hs1[(long)c1 * H1 + t];
        a2 += g_hs1[(long)c2 * H1 + t];
        a3 += g_hs1[(long)c3 * H1 + t];
    }
    for (; i < e0; i++) a0 += g_hs1[(long)g_col[i] * H1 + t];
    float a = (a0 + a1) + (a2 + a3);
    float h = fmaxf(g_dis[n] * (a + g_hs1[(long)n * H1 + t]) + __ldg(&b1[t]), 0.f);
    g_acc1[(long)n * H1 + t] = h;
}

// ---------- CSR aggregation layer2 + finish + classifier ---------------------
__global__ __launch_bounds__(64) void k_agg2(
    const float* __restrict__ b2, const float* __restrict__ Wc,
    const float* __restrict__ bc, float* __restrict__ out) {
    const int n = blockIdx.x, t = threadIdx.x;
    const int s0 = g_rowptr[n], e0 = g_rowptr[n + 1];
    float a0 = 0.f, a1 = 0.f, a2 = 0.f, a3 = 0.f;
    int i = s0;
    for (; i + 4 <= e0; i += 4) {
        int c0 = g_col[i], c1 = g_col[i + 1], c2 = g_col[i + 2], c3 = g_col[i + 3];
        a0 += g_hs2[(long)c0 * H2 + t];
        a1 += g_hs2[(long)c1 * H2 + t];
        a2 += g_hs2[(long)c2 * H2 + t];
        a3 += g_hs2[(long)c3 * H2 + t];
    }
    for (; i < e0; i++) a0 += g_hs2[(long)g_col[i] * H2 + t];
    float a = (a0 + a1) + (a2 + a3);
    float h = fmaxf(g_dis[n] * (a + g_hs2[(long)n * H2 + t]) + __ldg(&b2[t]), 0.f);

    const int lane = t & 31, w = t >> 5;
    __shared__ float sred[NC];
    float p[NC];
    #pragma unroll
    for (int c = 0; c < NC; c++) {
        float v = h * __ldg(&Wc[t * NC + c]);
        #pragma unroll
        for (int o = 16; o; o >>= 1) v += __shfl_xor_sync(0xFFFFFFFFu, v, o);
        p[c] = v;
    }
    if (w == 1 && lane == 0) {
        #pragma unroll
        for (int c = 0; c < NC; c++) sred[c] = p[c];
    }
    __syncthreads();
    if (w == 0 && lane == 0) {
        #pragma unroll
        for (int c = 0; c < NC; c++)
            out[(long)n * NC + c] = p[c] + sred[c] + __ldg(&bc[c]);
    }
}

// ---------------- launch ------------------------------------------------------
extern "C" void kernel_launch(void* const* d_in, const int* in_sizes, int n_in,
                              void* d_out, int out_size)
{
    const float* x  = (const float*)d_in[0];
    const void*  ei = d_in[1];
    const float* W1 = (const float*)d_in[2];
    const float* b1 = (const float*)d_in[3];
    const float* W2 = (const float*)d_in[4];
    const float* b2 = (const float*)d_in[5];
    const float* Wc = (const float*)d_in[6];
    const float* bc = (const float*)d_in[7];
    float* out = (float*)d_out;

    const int E = in_sizes[1] / 2;

    constexpr int SMEM1 = 2 * (2 * 128 + 2 * H1) * 80;  // 81920
    constexpr int SMEM2 = 2 * (2 * 128 + 2 * H2) * 80;  // 61440

    static float *p_hs1 = nullptr, *p_acc1 = nullptr, *p_hs2 = nullptr;
    static __nv_bfloat16 *p_w1h = nullptr, *p_w1l = nullptr, *p_w2h = nullptr, *p_w2l = nullptr;
    if (!p_hs1) {
        cudaGetSymbolAddress((void**)&p_hs1,  g_hs1);
        cudaGetSymbolAddress((void**)&p_acc1, g_acc1);
        cudaGetSymbolAddress((void**)&p_hs2,  g_hs2);
        cudaGetSymbolAddress((void**)&p_w1h,  g_W1t_hi);
        cudaGetSymbolAddress((void**)&p_w1l,  g_W1t_lo);
        cudaGetSymbolAddress((void**)&p_w2h,  g_W2t_hi);
        cudaGetSymbolAddress((void**)&p_w2l,  g_W2t_lo);
        cudaFuncSetAttribute(k_mm<H1, FIN, K1PAD>,
                             cudaFuncAttributeMaxDynamicSharedMemorySize, SMEM1);
        cudaFuncSetAttribute(k_mm<H2, H1, H1>,
                             cudaFuncAttributeMaxDynamicSharedMemorySize, SMEM2);
    }

    const int grid = (NNODES + 127) / 128;  // 782

    // 1: probe + zero hist + weight split
    k_probe_prep<<<512, 256>>>((const unsigned*)ei, W1, W2);
    // 2: degree histogram
    k_degree<<<(E + 255) / 256, 256>>>(ei, E);
    // 3: block sums + dis
    k_scanA<<<NB, 256>>>();
    // 4: layer-1 GEMM  (ncu -s 5 -c 1 window)
    k_mm<H1, FIN, K1PAD><<<grid, 256, SMEM1>>>(x, p_w1h, p_w1l, p_hs1, NNODES);
    // 5-7: finish CSR build
    k_scanB<<<1, 512>>>();
    k_scanC<<<NB, 256>>>();
    k_fill<<<(E + 255) / 256, 256>>>(ei, E);
    // 8: layer-1 aggregation + relu (writes h into acc1)
    k_agg1<<<NNODES, 128>>>(b1);
    // 9: layer-2 GEMM
    k_mm<H2, H1, H1><<<grid, 256, SMEM2>>>(p_acc1, p_w2h, p_w2l, p_hs2, NNODES);
    // 10: layer-2 aggregation + relu + classifier
    k_agg2<<<NNODES, 64>>>(b2, Wc, bc, out);
}

// round 8
// speedup vs baseline: 2.5266x; 1.2971x over previous
#include <cuda_runtime.h>
#include <cuda_bf16.h>
#include <cstdint>

// Problem constants (fixed by the dataset)
#define NNODES 100000
#define FIN    500
#define H1     128
#define H2     64
#define NC     10
#define K1PAD  512
#define EMAX   1700000
#define NB     391          // ceil(NNODES/256)

// ---------------- scratch (device globals; no allocs allowed) ----------------
__device__ __align__(16) float g_dis [NNODES];
__device__ __align__(16) float g_hs1 [NNODES * H1];
__device__ __align__(16) float g_acc1[NNODES * H1];
__device__ __align__(16) float g_hs2 [NNODES * H2];
__device__ __align__(16) __nv_bfloat16 g_W1t_hi[H1 * K1PAD];
__device__ __align__(16) __nv_bfloat16 g_W1t_lo[H1 * K1PAD];
__device__ __align__(16) __nv_bfloat16 g_W2t_hi[H2 * H1];
__device__ __align__(16) __nv_bfloat16 g_W2t_lo[H2 * H1];
__device__ int g_cnt   [NNODES];
__device__ int g_part  [512];
__device__ int g_rowptr[NNODES + 1];
__device__ int g_cursor[NNODES];
__device__ int g_col   [EMAX];
__device__ int g_is64;

__device__ __forceinline__ uint32_t smem_u32(const void* p) {
    uint32_t a;
    asm("{ .reg .u64 t; cvta.to.shared.u64 t, %1; cvt.u32.u64 %0, t; }" : "=r"(a) : "l"(p));
    return a;
}
__device__ __forceinline__ void ldm_x4(uint32_t* r, uint32_t addr) {
    asm volatile("ldmatrix.sync.aligned.m8n8.x4.shared.b16 {%0,%1,%2,%3}, [%4];"
        : "=r"(r[0]), "=r"(r[1]), "=r"(r[2]), "=r"(r[3]) : "r"(addr));
}
__device__ __forceinline__ void mma_bf16(float* c, const uint32_t* a, const uint32_t* b) {
    asm volatile("mma.sync.aligned.m16n8k16.row.col.f32.bf16.bf16.f32 "
        "{%0,%1,%2,%3}, {%4,%5,%6,%7}, {%8,%9}, {%0,%1,%2,%3};"
        : "+f"(c[0]), "+f"(c[1]), "+f"(c[2]), "+f"(c[3])
        : "r"(a[0]), "r"(a[1]), "r"(a[2]), "r"(a[3]), "r"(b[0]), "r"(b[1]));
}
__device__ __forceinline__ void cp16(uint32_t dst, const void* src) {
    asm volatile("cp.async.cg.shared.global [%0], [%1], 16;" :: "r"(dst), "l"(src));
}
__device__ __forceinline__ int eidx(const void* __restrict__ ei, long pos) {
    if (g_is64) return (int)((const long long*)ei)[pos];
    return ((const int*)ei)[pos];
}

// ---------- launch 1: probe dtype + zero histogram + weight split ------------
__global__ void k_probe_prep(const unsigned* __restrict__ w,
                             const float* __restrict__ W1,
                             const float* __restrict__ W2) {
    if (blockIdx.x == 0) {
        __shared__ unsigned red[256];
        unsigned o = 0;
        for (int i = threadIdx.x; i < 1024; i += 256) o |= w[2 * i + 1];
        red[threadIdx.x] = o;
        __syncthreads();
        for (int s = 128; s; s >>= 1) {
            if (threadIdx.x < s) red[threadIdx.x] |= red[threadIdx.x + s];
            __syncthreads();
        }
        if (threadIdx.x == 0) g_is64 = (red[0] == 0u) ? 1 : 0;
    }
    int i = blockIdx.x * blockDim.x + threadIdx.x;
    int stride = gridDim.x * blockDim.x;
    for (int j = i; j < NNODES; j += stride) g_cnt[j] = 0;
    for (int j = i; j < H1 * K1PAD; j += stride) {
        int n = j / K1PAD, k = j % K1PAD;
        float v = (k < FIN) ? W1[(long)k * H1 + n] : 0.f;
        __nv_bfloat16 h = __float2bfloat16(v);
        g_W1t_hi[j] = h;
        g_W1t_lo[j] = __float2bfloat16(v - __bfloat162float(h));
    }
    for (int j = i; j < H2 * H1; j += stride) {
        int n = j / H1, k = j % H1;
        float v = W2[(long)k * H2 + n];
        __nv_bfloat16 h = __float2bfloat16(v);
        g_W2t_hi[j] = h;
        g_W2t_lo[j] = __float2bfloat16(v - __bfloat162float(h));
    }
}

// ---------- launch 2: degree histogram --------------------------------------
__global__ void k_degree(const void* __restrict__ ei, int E) {
    int i = blockIdx.x * blockDim.x + threadIdx.x;
    if (i < E) atomicAdd(&g_cnt[eidx(ei, (long)E + i)], 1);
}

// ---------- launch 3: block sums + dis = rsqrt(cnt+1) ------------------------
__global__ void k_scanA() {
    int i = blockIdx.x * 256 + threadIdx.x;
    int v = (i < NNODES) ? g_cnt[i] : 0;
    if (i < NNODES) g_dis[i] = rsqrtf((float)v + 1.0f);
    __shared__ int s[256];
    s[threadIdx.x] = v;
    __syncthreads();
    for (int o = 128; o; o >>= 1) {
        if (threadIdx.x < o) s[threadIdx.x] += s[threadIdx.x + o];
        __syncthreads();
    }
    if (threadIdx.x == 0) g_part[blockIdx.x] = s[0];
}

// ---------- launch 5: scan the 391 block partials (exclusive) ----------------
__global__ void k_scanB() {
    __shared__ int s[512];
    int t = threadIdx.x;
    int v = (t < NB) ? g_part[t] : 0;
    s[t] = v;
    __syncthreads();
    for (int o = 1; o < 512; o <<= 1) {
        int x = (t >= o) ? s[t - o] : 0;
        __syncthreads();
        s[t] += x;
        __syncthreads();
    }
    if (t < NB) g_part[t] = s[t] - v;
}

// ---------- launch 6: per-element exclusive scan -> rowptr + cursor ----------
__global__ void k_scanC() {
    int b = blockIdx.x, t = threadIdx.x, i = b * 256 + t;
    int v = (i < NNODES) ? g_cnt[i] : 0;
    __shared__ int s[256];
    s[t] = v;
    __syncthreads();
    for (int o = 1; o < 256; o <<= 1) {
        int x = (t >= o) ? s[t - o] : 0;
        __syncthreads();
        s[t] += x;
        __syncthreads();
    }
    int excl = g_part[b] + s[t] - v;
    if (i < NNODES) {
        g_rowptr[i] = excl;
        g_cursor[i] = excl;
        if (i == NNODES - 1) g_rowptr[NNODES] = excl + v;
    }
}

// ---------- launch 7: CSR fill (col = src grouped by dst) --------------------
__global__ void k_fill(const void* __restrict__ ei, int E) {
    int i = blockIdx.x * blockDim.x + threadIdx.x;
    if (i < E) {
        int s = eidx(ei, i);
        int d = eidx(ei, (long)E + i);
        int pos = atomicAdd(&g_cursor[d], 1);
        g_col[pos] = s;
    }
}

// ---------------- HMMA split-bf16 GEMM: Cout = dis[row] * (A @ Bt^T) ---------
// BM=64 tiles, NCTA CTAs/SM, double-buffered SMEM, cp.async B, reg-staged A.
template <int BM, int BN, int KREAL, int KPAD, int NCTA>
__global__ __launch_bounds__(256, NCTA) void k_mm(
    const float* __restrict__ A, const __nv_bfloat16* __restrict__ Bh,
    const __nv_bfloat16* __restrict__ Bl, float* __restrict__ Cout, int M)
{
    constexpr int BK = 32, C = KPAD / BK;
    constexpr int WN = BN / 4;
    constexpr int NT = WN / 8;
    constexpr int MT = BM / 32;          // rows per warp = MT*16
    constexpr int ROWB = 80;             // 40 bf16, conflict-free stride
    constexpr int STG = (2 * BM + 2 * BN) * ROWB;
    constexpr uint32_t oAl = BM * ROWB;
    constexpr uint32_t oBh = 2 * BM * ROWB;
    constexpr uint32_t oBl = 2 * BM * ROWB + BN * ROWB;
    constexpr int TPR  = 256 / BM;       // threads per A row
    constexpr int C4PT = 8 / TPR;        // float4s per thread

    extern __shared__ char sm[];
    const uint32_t u0 = smem_u32(sm);

    const int tid = threadIdx.x, wid = tid >> 5, lane = tid & 31;
    const int wm = wid >> 2, wn = wid & 3;
    const int rowBase = blockIdx.x * BM;

    float acc[MT][NT][4];
    #pragma unroll
    for (int m = 0; m < MT; m++)
        #pragma unroll
        for (int n = 0; n < NT; n++)
            #pragma unroll
            for (int j = 0; j < 4; j++) acc[m][n][j] = 0.f;

    float4 aReg[C4PT];
    const int aRow = tid / TPR;
    const int aC4b = (tid % TPR) * C4PT;

    auto loadA = [&](int c) {
        const int k0 = c * BK;
        const int grow = rowBase + aRow;
        #pragma unroll
        for (int i = 0; i < C4PT; i++) {
            int gcol = k0 + (aC4b + i) * 4;
            float4 v = make_float4(0.f, 0.f, 0.f, 0.f);
            if (grow < M) {
                if (gcol + 4 <= KREAL) {
                    v = *reinterpret_cast<const float4*>(A + (long)grow * KREAL + gcol);
                } else if (gcol < KREAL) {
                    float t[4];
                    #pragma unroll
                    for (int u = 0; u < 4; u++)
                        t[u] = (gcol + u < KREAL) ? A[(long)grow * KREAL + gcol + u] : 0.f;
                    v = make_float4(t[0], t[1], t[2], t[3]);
                }
            }
            aReg[i] = v;
        }
    };
    auto storeA = [&](int s) {
        char* ah = sm + s * STG + aRow * ROWB + aC4b * 8;
        char* al = ah + oAl;
        #pragma unroll
        for (int i = 0; i < C4PT; i++) {
            float4 v = aReg[i];
            __nv_bfloat16 hx = __float2bfloat16(v.x), hy = __float2bfloat16(v.y);
            __nv_bfloat16 hz = __float2bfloat16(v.z), hw = __float2bfloat16(v.w);
            unsigned h0 = ((unsigned)__bfloat16_as_ushort(hy) << 16) | __bfloat16_as_ushort(hx);
            unsigned h1 = ((unsigned)__bfloat16_as_ushort(hw) << 16) | __bfloat16_as_ushort(hz);
            __nv_bfloat16 lx = __float2bfloat16(v.x - __bfloat162float(hx));
            __nv_bfloat16 ly = __float2bfloat16(v.y - __bfloat162float(hy));
            __nv_bfloat16 lz = __float2bfloat16(v.z - __bfloat162float(hz));
            __nv_bfloat16 lw = __float2bfloat16(v.w - __bfloat162float(hw));
            unsigned l0 = ((unsigned)__bfloat16_as_ushort(ly) << 16) | __bfloat16_as_ushort(lx);
            unsigned l1 = ((unsigned)__bfloat16_as_ushort(lw) << 16) | __bfloat16_as_ushort(lz);
            *reinterpret_cast<uint2*>(ah + i * 8) = make_uint2(h0, h1);
            *reinterpret_cast<uint2*>(al + i * 8) = make_uint2(l0, l1);
        }
    };
    auto cpB = [&](int c, int s) {
        #pragma unroll
        for (int i = tid; i < BN * 8; i += 256) {
            int mat = (i >= BN * 4) ? 1 : 0;
            int j = i - mat * BN * 4;
            int row = j >> 2, u = j & 3;
            const char* src = (const char*)(mat ? Bl : Bh) +
                              (long)row * (KPAD * 2) + (long)c * 64 + u * 16;
            uint32_t dst = u0 + s * STG + (mat ? oBl : oBh) + row * ROWB + u * 16;
            cp16(dst, src);
        }
    };

    const int lRow = ((lane >> 3) & 1) * 8 + (lane & 7);
    const int lKof = (lane >> 4) * 16;

    auto compute = [&](int s) {
        const uint32_t base = u0 + s * STG;
        #pragma unroll
        for (int kk = 0; kk < 2; kk++) {
            uint32_t bfH[NT][2], bfL[NT][2];
            #pragma unroll
            for (int np = 0; np < NT / 2; np++) {
                uint32_t off = base + oBh + (uint32_t)((wn * WN + np * 16 + lRow) * ROWB + kk * 32 + lKof);
                uint32_t rH[4], rL[4];
                ldm_x4(rH, off);
                ldm_x4(rL, off + (oBl - oBh));
                bfH[np * 2][0] = rH[0]; bfH[np * 2][1] = rH[2];
                bfH[np * 2 + 1][0] = rH[1]; bfH[np * 2 + 1][1] = rH[3];
                bfL[np * 2][0] = rL[0]; bfL[np * 2][1] = rL[2];
                bfL[np * 2 + 1][0] = rL[1]; bfL[np * 2 + 1][1] = rL[3];
            }
            #pragma unroll
            for (int mt = 0; mt < MT; mt++) {
                uint32_t off = base + (uint32_t)((wm * (MT * 16) + mt * 16 + lRow) * ROWB + kk * 32 + lKof);
                uint32_t afH[4], afL[4];
                ldm_x4(afH, off);
                ldm_x4(afL, off + oAl);
                #pragma unroll
                for (int nt = 0; nt < NT; nt++) {
                    mma_bf16(acc[mt][nt], afH, bfH[nt]);
                    mma_bf16(acc[mt][nt], afH, bfL[nt]);
                    mma_bf16(acc[mt][nt], afL, bfH[nt]);
                }
            }
        }
    };

    // prologue: chunk 0 into stage 0
    loadA(0);
    cpB(0, 0);
    storeA(0);
    asm volatile("cp.async.commit_group;");
    asm volatile("cp.async.wait_group 0;");
    __syncthreads();

    for (int c = 0; c < C; c++) {
        const int s = c & 1;
        if (c + 1 < C) {
            loadA(c + 1);
            cpB(c + 1, s ^ 1);
            asm volatile("cp.async.commit_group;");
        }
        compute(s);
        if (c + 1 < C) {
            storeA(s ^ 1);
            asm volatile("cp.async.wait_group 0;");
            __syncthreads();
        }
    }

    #pragma unroll
    for (int mt = 0; mt < MT; mt++) {
        int r0 = rowBase + wm * (MT * 16) + mt * 16 + (lane >> 2);
        int r1 = r0 + 8;
        float s0 = (r0 < M) ? g_dis[r0] : 0.f;
        float s1 = (r1 < M) ? g_dis[r1] : 0.f;
        #pragma unroll
        for (int nt = 0; nt < NT; nt++) {
            int col = wn * WN + nt * 8 + 2 * (lane & 3);
            if (r0 < M) {
                float2 v = make_float2(acc[mt][nt][0] * s0, acc[mt][nt][1] * s0);
                *reinterpret_cast<float2*>(Cout + (long)r0 * BN + col) = v;
            }
            if (r1 < M) {
                float2 v = make_float2(acc[mt][nt][2] * s1, acc[mt][nt][3] * s1);
                *reinterpret_cast<float2*>(Cout + (long)r1 * BN + col) = v;
            }
        }
    }
}

// ---------- CSR aggregation layer1 + finish: warp = node, lane = float4 ------
__global__ __launch_bounds__(256) void k_agg1(const float* __restrict__ b1) {
    const int wid = threadIdx.x >> 5, lane = threadIdx.x & 31;
    const int n = blockIdx.x * 8 + wid;
    if (n >= NNODES) return;
    const int s0 = g_rowptr[n], e0 = g_rowptr[n + 1];
    const float4* __restrict__ hs = reinterpret_cast<const float4*>(g_hs1);
    float4 a0 = make_float4(0.f, 0.f, 0.f, 0.f), a1 = a0, a2 = a0, a3 = a0;
    int i = s0;
    for (; i + 4 <= e0; i += 4) {
        int c0 = g_col[i], c1 = g_col[i + 1], c2 = g_col[i + 2], c3 = g_col[i + 3];
        float4 v0 = hs[(long)c0 * 32 + lane];
        float4 v1 = hs[(long)c1 * 32 + lane];
        float4 v2 = hs[(long)c2 * 32 + lane];
        float4 v3 = hs[(long)c3 * 32 + lane];
        a0.x += v0.x; a0.y += v0.y; a0.z += v0.z; a0.w += v0.w;
        a1.x += v1.x; a1.y += v1.y; a1.z += v1.z; a1.w += v1.w;
        a2.x += v2.x; a2.y += v2.y; a2.z += v2.z; a2.w += v2.w;
        a3.x += v3.x; a3.y += v3.y; a3.z += v3.z; a3.w += v3.w;
    }
    for (; i < e0; i++) {
        float4 v = hs[(long)g_col[i] * 32 + lane];
        a0.x += v.x; a0.y += v.y; a0.z += v.z; a0.w += v.w;
    }
    float4 a = make_float4((a0.x + a1.x) + (a2.x + a3.x), (a0.y + a1.y) + (a2.y + a3.y),
                           (a0.z + a1.z) + (a2.z + a3.z), (a0.w + a1.w) + (a2.w + a3.w));
    float s = g_dis[n];
    float4 self = hs[(long)n * 32 + lane];
    float4 bb = __ldg(reinterpret_cast<const float4*>(b1) + lane);
    float4 r;
    r.x = fmaxf(s * (a.x + self.x) + bb.x, 0.f);
    r.y = fmaxf(s * (a.y + self.y) + bb.y, 0.f);
    r.z = fmaxf(s * (a.z + self.z) + bb.z, 0.f);
    r.w = fmaxf(s * (a.w + self.w) + bb.w, 0.f);
    reinterpret_cast<float4*>(g_acc1)[(long)n * 32 + lane] = r;
}

// ---------- CSR aggregation layer2 + finish + classifier: warp = node --------
__global__ __launch_bounds__(256) void k_agg2(
    const float* __restrict__ b2, const float* __restrict__ Wc,
    const float* __restrict__ bc, float* __restrict__ out) {
    const int wid = threadIdx.x >> 5, lane = threadIdx.x & 31;
    const int n = blockIdx.x * 8 + wid;
    if (n >= NNODES) return;
    const int s0 = g_rowptr[n], e0 = g_rowptr[n + 1];
    const float2* __restrict__ hs = reinterpret_cast<const float2*>(g_hs2);
    float2 a0 = make_float2(0.f, 0.f), a1 = a0, a2 = a0, a3 = a0;
    int i = s0;
    for (; i + 4 <= e0; i += 4) {
        int c0 = g_col[i], c1 = g_col[i + 1], c2 = g_col[i + 2], c3 = g_col[i + 3];
        float2 v0 = hs[(long)c0 * 32 + lane];
        float2 v1 = hs[(long)c1 * 32 + lane];
        float2 v2 = hs[(long)c2 * 32 + lane];
        float2 v3 = hs[(long)c3 * 32 + lane];
        a0.x += v0.x; a0.y += v0.y;
        a1.x += v1.x; a1.y += v1.y;
        a2.x += v2.x; a2.y += v2.y;
        a3.x += v3.x; a3.y += v3.y;
    }
    for (; i < e0; i++) {
        float2 v = hs[(long)g_col[i] * 32 + lane];
        a0.x += v.x; a0.y += v.y;
    }
    float ax = (a0.x + a1.x) + (a2.x + a3.x);
    float ay = (a0.y + a1.y) + (a2.y + a3.y);
    float s = g_dis[n];
    float2 self = hs[(long)n * 32 + lane];
    float2 bb = __ldg(reinterpret_cast<const float2*>(b2) + lane);
    float hx = fmaxf(s * (ax + self.x) + bb.x, 0.f);
    float hy = fmaxf(s * (ay + self.y) + bb.y, 0.f);

    float p[NC];
    #pragma unroll
    for (int c = 0; c < NC; c++) {
        float v = hx * __ldg(&Wc[(2 * lane) * NC + c]) + hy * __ldg(&Wc[(2 * lane + 1) * NC + c]);
        #pragma unroll
        for (int o = 16; o; o >>= 1) v += __shfl_xor_sync(0xFFFFFFFFu, v, o);
        p[c] = v;
    }
    if (lane < NC) out[(long)n * NC + lane] = p[lane] + __ldg(&bc[lane]);
}

// ---------------- launch ------------------------------------------------------
extern "C" void kernel_launch(void* const* d_in, const int* in_sizes, int n_in,
                              void* d_out, int out_size)
{
    const float* x  = (const float*)d_in[0];
    const void*  ei = d_in[1];
    const float* W1 = (const float*)d_in[2];
    const float* b1 = (const float*)d_in[3];
    const float* W2 = (const float*)d_in[4];
    const float* b2 = (const float*)d_in[5];
    const float* Wc = (const float*)d_in[6];
    const float* bc = (const float*)d_in[7];
    float* out = (float*)d_out;

    const int E = in_sizes[1] / 2;

    constexpr int SMEM1 = 2 * (2 * 64 + 2 * H1) * 80;  // 61440
    constexpr int SMEM2 = 2 * (2 * 64 + 2 * H2) * 80;  // 40960

    static float *p_hs1 = nullptr, *p_acc1 = nullptr, *p_hs2 = nullptr;
    static __nv_bfloat16 *p_w1h = nullptr, *p_w1l = nullptr, *p_w2h = nullptr, *p_w2l = nullptr;
    if (!p_hs1) {
        cudaGetSymbolAddress((void**)&p_hs1,  g_hs1);
        cudaGetSymbolAddress((void**)&p_acc1, g_acc1);
        cudaGetSymbolAddress((void**)&p_hs2,  g_hs2);
        cudaGetSymbolAddress((void**)&p_w1h,  g_W1t_hi);
        cudaGetSymbolAddress((void**)&p_w1l,  g_W1t_lo);
        cudaGetSymbolAddress((void**)&p_w2h,  g_W2t_hi);
        cudaGetSymbolAddress((void**)&p_w2l,  g_W2t_lo);
        cudaFuncSetAttribute(k_mm<64, H1, FIN, K1PAD, 3>,
                             cudaFuncAttributeMaxDynamicSharedMemorySize, SMEM1);
        cudaFuncSetAttribute(k_mm<64, H2, H1, H1, 4>,
                             cudaFuncAttributeMaxDynamicSharedMemorySize, SMEM2);
    }

    const int grid = (NNODES + 63) / 64;   // 1563
    const int gridAgg = (NNODES + 7) / 8;  // 12500

    // 1: probe + zero hist + weight split
    k_probe_prep<<<512, 256>>>((const unsigned*)ei, W1, W2);
    // 2: degree histogram
    k_degree<<<(E + 255) / 256, 256>>>(ei, E);
    // 3: block sums + dis
    k_scanA<<<NB, 256>>>();
    // 4: layer-1 GEMM  (ncu -s 5 -c 1 window)
    k_mm<64, H1, FIN, K1PAD, 3><<<grid, 256, SMEM1>>>(x, p_w1h, p_w1l, p_hs1, NNODES);
    // 5-7: finish CSR build
    k_scanB<<<1, 512>>>();
    k_scanC<<<NB, 256>>>();
    k_fill<<<(E + 255) / 256, 256>>>(ei, E);
    // 8: layer-1 aggregation + relu (writes h into acc1)
    k_agg1<<<gridAgg, 256>>>(b1);
    // 9: layer-2 GEMM
    k_mm<64, H2, H1, H1, 4><<<grid, 256, SMEM2>>>(p_acc1, p_w2h, p_w2l, p_hs2, NNODES);
    // 10: layer-2 aggregation + relu + classifier
    k_agg2<<<gridAgg, 256>>>(b2, Wc, bc, out);
}